// round 5
// baseline (speedup 1.0000x reference)
#include <cuda_runtime.h>
#include <cuda_bf16.h>
#include <cstdint>

// ---------------------------------------------------------------------------
// VariationalEncoder (3-layer GCN VGAE encoder), fixed shapes:
//   N = 100000 nodes, E = 1600000 edges, 512 -> 128 -> {64, 64}
// Pipeline per launch (graph-capturable, allocation-free):
//   0. detect edge_index dtype (int32 vs int64)     -> g_is64
//   1. deg histogram (self-loop included)           -> g_deg
//   2. single-block scan: rowstart/cursor/dinv      -> g_rowstart, g_dinv
//   3. CSR scatter (edges grouped by dst)           -> g_csr
//   4. GEMM1: t1 = x @ W1                 [100k,128]
//   5. agg1:  h = relu(A_hat t1 + b1)     (gather-side, warp per node)
//   6. pack Wcat = [W_mu | W_ls]          [128,128]
//   7. GEMM2: t2 = h @ Wcat               [100k,128]
//   8. agg2:  (mu, logstd) = A_hat t2 + (b_mu, b_ls)  -> d_out
// R4: edge_index was being read as int64 while JAX (x64 disabled) emits
// int32 -> OOB reads + wild atomics -> device trap 717. Now detected at
// runtime; index fetches are dtype-branched and bounds-guarded.
// ---------------------------------------------------------------------------

#define N_NODES 100000
#define N_EDGES 1600000
#define C_IN    512
#define C_HID   128          // 2 * OUT_CH
#define C_OUT   64

// -------------------- device scratch (no allocations allowed) --------------
__device__ int    g_is64;
__device__ int    g_deg[N_NODES];
__device__ float  g_dinv[N_NODES];
__device__ int    g_rowstart[N_NODES + 1];
__device__ int    g_cursor[N_NODES];
__device__ int    g_csr[N_EDGES];
__device__ float4 g_t1[N_NODES * 32];   // [N,128] as float4
__device__ float4 g_h [N_NODES * 32];   // [N,128]
__device__ float4 g_t2[N_NODES * 32];   // [N,128]
__device__ float  g_wcat[C_HID * C_HID]; // [128,128] = [W_mu | W_ls]

// -------------------- dtype detection --------------------------------------
// int64 node ids (< 100000, nonneg, little-endian) have every odd 32-bit
// word == 0. Random int32 ids make 8 consecutive zero odd-words ~1e-20.
__global__ void k_detect(const unsigned int* __restrict__ w) {
    bool is64 = true;
    #pragma unroll
    for (int i = 0; i < 8; i++)
        if (w[2 * i + 1] != 0u) is64 = false;
    g_is64 = is64 ? 1 : 0;
}

// row: 0 = src, 1 = dst
__device__ __forceinline__ int edge_at(const void* __restrict__ ei,
                                       int row, int e) {
    if (g_is64)
        return (int)((const long long*)ei)[(size_t)row * N_EDGES + e];
    return ((const int*)ei)[(size_t)row * N_EDGES + e];
}

// -------------------- graph preprocessing ----------------------------------
__global__ void k_set_deg(void) {
    int i = blockIdx.x * blockDim.x + threadIdx.x;
    if (i < N_NODES) g_deg[i] = 1;  // self-loop
}

__global__ void k_count(const void* __restrict__ ei) {
    int e = blockIdx.x * blockDim.x + threadIdx.x;
    if (e < N_EDGES) {
        int d = edge_at(ei, 1, e);
        if (d >= 0 && d < N_NODES) atomicAdd(&g_deg[d], 1);
    }
}

// Single-block serial-chunk scan over 100001 entries. Also writes dinv and
// initializes per-node scatter cursors.
__global__ void k_scan(void) {
    __shared__ int s[1024];
    __shared__ int carry;
    int tid = threadIdx.x;
    if (tid == 0) carry = 0;
    __syncthreads();
    for (int base = 0; base < N_NODES; base += 1024) {
        int idx = base + tid;
        int deg = (idx < N_NODES) ? g_deg[idx] : 1;
        int v   = (idx < N_NODES) ? (deg - 1) : 0;   // real-edge count
        if (idx < N_NODES) g_dinv[idx] = rsqrtf((float)deg);
        s[tid] = v;
        __syncthreads();
        #pragma unroll
        for (int off = 1; off < 1024; off <<= 1) {
            int t = (tid >= off) ? s[tid - off] : 0;
            __syncthreads();
            s[tid] += t;
            __syncthreads();
        }
        int incl = s[tid];
        int excl = carry + incl - v;
        if (idx < N_NODES) {
            g_rowstart[idx] = excl;
            g_cursor[idx]   = excl;
        }
        __syncthreads();
        if (tid == 1023) carry += incl;
        __syncthreads();
    }
    if (tid == 0) g_rowstart[N_NODES] = carry;
}

__global__ void k_scatter(const void* __restrict__ ei) {
    int e = blockIdx.x * blockDim.x + threadIdx.x;
    if (e < N_EDGES) {
        int sidx = edge_at(ei, 0, e);
        int d    = edge_at(ei, 1, e);
        if (d >= 0 && d < N_NODES && sidx >= 0 && sidx < N_NODES) {
            int pos = atomicAdd(&g_cursor[d], 1);
            if (pos >= 0 && pos < N_EDGES) g_csr[pos] = sidx;
        }
    }
}

// -------------------- GEMM: C[M,128] = A[M,K] @ B[K,128] -------------------
// BM=128, BN=128(=full), BK=16; 256 threads, 8x8 per-thread microtile.
__global__ void __launch_bounds__(256)
k_gemm(const float* __restrict__ A, const float* __restrict__ B,
       float* __restrict__ C, int M, int K) {
    __shared__ float As[16][132];   // transposed, +4 pad: conflict-free stores
    __shared__ float Bs[16][128];

    int tid = threadIdx.x;
    int m0  = blockIdx.x * 128;
    int tx  = tid & 15;             // N direction (8 cols each)
    int ty  = tid >> 4;             // M direction (8 rows each)

    // A-tile load mapping: 128 rows x 16 cols = 512 float4; 2 per thread
    int ar  = tid >> 2;             // 0..63 (also +64)
    int ac4 = (tid & 3) * 4;        // k offset within tile
    // B-tile load mapping: 16 rows x 128 cols = 512 float4; 2 per thread
    int bk  = tid >> 4;             // 0..15
    int bc  = (tid & 15) * 4;       // col (floats), second half at +64

    float acc[8][8];
    #pragma unroll
    for (int i = 0; i < 8; i++)
        #pragma unroll
        for (int j = 0; j < 8; j++) acc[i][j] = 0.f;

    for (int k0 = 0; k0 < K; k0 += 16) {
        float4 a0 = make_float4(0.f, 0.f, 0.f, 0.f);
        float4 a1 = a0;
        int r0 = m0 + ar, r1 = r0 + 64;
        if (r0 < M) a0 = *(const float4*)&A[(size_t)r0 * K + k0 + ac4];
        if (r1 < M) a1 = *(const float4*)&A[(size_t)r1 * K + k0 + ac4];
        float4 b0 = *(const float4*)&B[(size_t)(k0 + bk) * 128 + bc];
        float4 b1 = *(const float4*)&B[(size_t)(k0 + bk) * 128 + bc + 64];

        __syncthreads();
        As[ac4 + 0][ar] = a0.x; As[ac4 + 1][ar] = a0.y;
        As[ac4 + 2][ar] = a0.z; As[ac4 + 3][ar] = a0.w;
        As[ac4 + 0][ar + 64] = a1.x; As[ac4 + 1][ar + 64] = a1.y;
        As[ac4 + 2][ar + 64] = a1.z; As[ac4 + 3][ar + 64] = a1.w;
        *(float4*)&Bs[bk][bc]      = b0;
        *(float4*)&Bs[bk][bc + 64] = b1;
        __syncthreads();

        #pragma unroll
        for (int kk = 0; kk < 16; kk++) {
            float a[8], b[8];
            #pragma unroll
            for (int i = 0; i < 8; i++) a[i] = As[kk][ty * 8 + i];
            #pragma unroll
            for (int j = 0; j < 8; j++) b[j] = Bs[kk][tx * 8 + j];
            #pragma unroll
            for (int i = 0; i < 8; i++)
                #pragma unroll
                for (int j = 0; j < 8; j++)
                    acc[i][j] = fmaf(a[i], b[j], acc[i][j]);
        }
    }

    #pragma unroll
    for (int i = 0; i < 8; i++) {
        int r = m0 + ty * 8 + i;
        if (r < M) {
            float4 v0 = make_float4(acc[i][0], acc[i][1], acc[i][2], acc[i][3]);
            float4 v1 = make_float4(acc[i][4], acc[i][5], acc[i][6], acc[i][7]);
            *(float4*)&C[(size_t)r * 128 + tx * 8]     = v0;
            *(float4*)&C[(size_t)r * 128 + tx * 8 + 4] = v1;
        }
    }
}

// -------------------- pack [W_mu | W_ls] -> g_wcat -------------------------
__global__ void k_packw(const float* __restrict__ Wmu,
                        const float* __restrict__ Wls) {
    int i = blockIdx.x * blockDim.x + threadIdx.x;
    if (i < C_HID * C_HID) {
        int k = i >> 7, j = i & 127;
        g_wcat[i] = (j < 64) ? Wmu[k * 64 + j] : Wls[k * 64 + (j - 64)];
    }
}

// -------------------- aggregation: warp per node, 128 channels -------------
// acc = dinv[d]^2 * t[d] + sum_e dinv[d]*dinv[src_e] * t[src_e]
__device__ __forceinline__ float4 agg_node(const float4* __restrict__ t,
                                           int d, int lane) {
    float dv = g_dinv[d];
    float4 v = t[d * 32 + lane];
    float w  = dv * dv;
    float4 acc = make_float4(w * v.x, w * v.y, w * v.z, w * v.w);
    int beg = g_rowstart[d], end = g_rowstart[d + 1];
    int i = beg;
    for (; i + 1 < end; i += 2) {   // unroll x2 for MLP on the L2 gathers
        int s0 = g_csr[i], s1 = g_csr[i + 1];
        float w0 = dv * g_dinv[s0];
        float w1 = dv * g_dinv[s1];
        float4 u0 = __ldg(&t[s0 * 32 + lane]);
        float4 u1 = __ldg(&t[s1 * 32 + lane]);
        acc.x += w0 * u0.x + w1 * u1.x;
        acc.y += w0 * u0.y + w1 * u1.y;
        acc.z += w0 * u0.z + w1 * u1.z;
        acc.w += w0 * u0.w + w1 * u1.w;
    }
    if (i < end) {
        int s0 = g_csr[i];
        float w0 = dv * g_dinv[s0];
        float4 u0 = __ldg(&t[s0 * 32 + lane]);
        acc.x += w0 * u0.x; acc.y += w0 * u0.y;
        acc.z += w0 * u0.z; acc.w += w0 * u0.w;
    }
    return acc;
}

__global__ void __launch_bounds__(256)
k_agg1(const float* __restrict__ b1) {
    int gw = (blockIdx.x * blockDim.x + threadIdx.x) >> 5;
    if (gw >= N_NODES) return;
    int lane = threadIdx.x & 31;
    float4 acc = agg_node(g_t1, gw, lane);
    float4 bb = *(const float4*)&b1[lane * 4];
    acc.x = fmaxf(acc.x + bb.x, 0.f);
    acc.y = fmaxf(acc.y + bb.y, 0.f);
    acc.z = fmaxf(acc.z + bb.z, 0.f);
    acc.w = fmaxf(acc.w + bb.w, 0.f);
    g_h[gw * 32 + lane] = acc;
}

__global__ void __launch_bounds__(256)
k_agg2(const float* __restrict__ b_mu, const float* __restrict__ b_ls,
       float* __restrict__ out) {
    int gw = (blockIdx.x * blockDim.x + threadIdx.x) >> 5;
    if (gw >= N_NODES) return;
    int lane = threadIdx.x & 31;
    float4 acc = agg_node(g_t2, gw, lane);
    int c = lane * 4;   // channel in the packed [mu | logstd] layout
    if (c < 64) {
        float4 bb = *(const float4*)&b_mu[c];
        acc.x += bb.x; acc.y += bb.y; acc.z += bb.z; acc.w += bb.w;
        *(float4*)&out[(size_t)gw * 64 + c] = acc;
    } else {
        float4 bb = *(const float4*)&b_ls[c - 64];
        acc.x += bb.x; acc.y += bb.y; acc.z += bb.z; acc.w += bb.w;
        *(float4*)&out[(size_t)N_NODES * 64 + (size_t)gw * 64 + (c - 64)] = acc;
    }
}

// -------------------- launch -----------------------------------------------
extern "C" void kernel_launch(void* const* d_in, const int* in_sizes, int n_in,
                              void* d_out, int out_size) {
    const float* x    = (const float*)d_in[0];
    const void*  ei   = d_in[1];                 // [2, E], int32 OR int64
    const float* W1   = (const float*)d_in[2];
    const float* b1   = (const float*)d_in[3];
    const float* Wmu  = (const float*)d_in[4];
    const float* bmu  = (const float*)d_in[5];
    const float* Wls  = (const float*)d_in[6];
    const float* bls  = (const float*)d_in[7];
    float*       out  = (float*)d_out;

    (void)in_sizes; (void)n_in; (void)out_size;

    // Resolve device scratch addresses (host shadow symbols are NOT device
    // pointers).
    void *p_t1 = nullptr, *p_h = nullptr, *p_t2 = nullptr, *p_wcat = nullptr;
    cudaGetSymbolAddress(&p_t1,   g_t1);
    cudaGetSymbolAddress(&p_h,    g_h);
    cudaGetSymbolAddress(&p_t2,   g_t2);
    cudaGetSymbolAddress(&p_wcat, g_wcat);

    // Graph preprocessing
    k_detect <<<1, 1>>>((const unsigned int*)ei);
    k_set_deg<<<(N_NODES + 255) / 256, 256>>>();
    k_count  <<<(N_EDGES + 255) / 256, 256>>>(ei);
    k_scan   <<<1, 1024>>>();
    k_scatter<<<(N_EDGES + 255) / 256, 256>>>(ei);

    // Layer 1
    k_gemm<<<(N_NODES + 127) / 128, 256>>>(x, W1, (float*)p_t1, N_NODES, C_IN);
    k_agg1<<<(N_NODES * 32 + 255) / 256, 256>>>(b1);

    // Layers 2+3 fused (mu | logstd)
    k_packw<<<(C_HID * C_HID + 255) / 256, 256>>>(Wmu, Wls);
    k_gemm<<<(N_NODES + 127) / 128, 256>>>((const float*)p_h, (const float*)p_wcat,
                                           (float*)p_t2, N_NODES, C_HID);
    k_agg2<<<(N_NODES * 32 + 255) / 256, 256>>>(bmu, bls, out);
}

// round 7
// speedup vs baseline: 1.2656x; 1.2656x over previous
#include <cuda_runtime.h>
#include <cuda_bf16.h>
#include <cstdint>

// ---------------------------------------------------------------------------
// VariationalEncoder (3-layer GCN VGAE encoder), fixed shapes:
//   N = 100000 nodes, E = 1600000 edges, 512 -> 128 -> {64, 64}
// R6 (resubmitted unchanged after infra failure):
//  * k_scan (171.7us on 1 block!) -> 3-kernel two-level scan (~8us).
//  * fp32 SIMT GEMMs -> bf16-split tensor-core GEMM (mma.sync.m16n8k16):
//    a = a_hi + a_lo (bf16), C = Ahi*Bhi + Ahi*Blo + Alo*Bhi  (~2^-17 rel err)
// ---------------------------------------------------------------------------

#define N_NODES 100000
#define N_EDGES 1600000
#define C_IN    512
#define C_HID   128
#define C_OUT   64
#define NB1     ((N_NODES + 1023) / 1024)   // 98 scan blocks

// -------------------- device scratch (no allocations allowed) --------------
__device__ int    g_is64;
__device__ int    g_deg[N_NODES];
__device__ float  g_dinv[N_NODES];
__device__ int    g_rowstart[N_NODES + 1];
__device__ int    g_cursor[N_NODES];
__device__ int    g_bsum[NB1];
__device__ int    g_boff[NB1 + 1];
__device__ int    g_csr[N_EDGES];
__device__ float4 g_t1[N_NODES * 32];   // [N,128] as float4
__device__ float4 g_h [N_NODES * 32];   // [N,128]
__device__ float4 g_t2[N_NODES * 32];   // [N,128]
__device__ float  g_wcat[C_HID * C_HID]; // [128,128] = [W_mu | W_ls]

// -------------------- dtype detection --------------------------------------
__global__ void k_detect(const unsigned int* __restrict__ w) {
    bool is64 = true;
    #pragma unroll
    for (int i = 0; i < 8; i++)
        if (w[2 * i + 1] != 0u) is64 = false;
    g_is64 = is64 ? 1 : 0;
}

__device__ __forceinline__ int edge_at(const void* __restrict__ ei,
                                       int row, int e) {
    if (g_is64)
        return (int)((const long long*)ei)[(size_t)row * N_EDGES + e];
    return ((const int*)ei)[(size_t)row * N_EDGES + e];
}

// -------------------- graph preprocessing ----------------------------------
__global__ void k_set_deg(void) {
    int i = blockIdx.x * blockDim.x + threadIdx.x;
    if (i < N_NODES) g_deg[i] = 1;  // self-loop
}

__global__ void k_count(const void* __restrict__ ei) {
    int e = blockIdx.x * blockDim.x + threadIdx.x;
    if (e < N_EDGES) {
        int d = edge_at(ei, 1, e);
        if (d >= 0 && d < N_NODES) atomicAdd(&g_deg[d], 1);
    }
}

// Two-level scan, phase 1: per-block (1024) exclusive scan + block sums.
__global__ void __launch_bounds__(1024) k_scan1(void) {
    int tid  = threadIdx.x;
    int idx  = blockIdx.x * 1024 + tid;
    int lane = tid & 31, wid = tid >> 5;
    int deg = (idx < N_NODES) ? g_deg[idx] : 1;
    int v   = (idx < N_NODES) ? (deg - 1) : 0;
    if (idx < N_NODES) g_dinv[idx] = rsqrtf((float)deg);

    int incl = v;
    #pragma unroll
    for (int off = 1; off < 32; off <<= 1) {
        int t = __shfl_up_sync(0xffffffffu, incl, off);
        if (lane >= off) incl += t;
    }
    __shared__ int wsum[32];
    if (lane == 31) wsum[wid] = incl;
    __syncthreads();
    if (wid == 0) {
        int s = wsum[lane];
        #pragma unroll
        for (int off = 1; off < 32; off <<= 1) {
            int t = __shfl_up_sync(0xffffffffu, s, off);
            if (lane >= off) s += t;
        }
        wsum[lane] = s;
    }
    __syncthreads();
    int woff = (wid > 0) ? wsum[wid - 1] : 0;
    int excl = woff + incl - v;
    if (idx < N_NODES) g_rowstart[idx] = excl;          // local-exclusive
    if (tid == 1023) g_bsum[blockIdx.x] = woff + incl;  // block total
}

// Phase 2: single block scans the 98 block sums (exclusive) + grand total.
__global__ void k_scan2(void) {
    __shared__ int s[128];
    int tid = threadIdx.x;
    int v = (tid < NB1) ? g_bsum[tid] : 0;
    s[tid] = v;
    __syncthreads();
    #pragma unroll
    for (int off = 1; off < 128; off <<= 1) {
        int t = (tid >= off) ? s[tid - off] : 0;
        __syncthreads();
        s[tid] += t;
        __syncthreads();
    }
    int incl = s[tid];
    if (tid < NB1) g_boff[tid] = incl - v;
    if (tid == NB1 - 1) g_boff[NB1] = incl;
}

// Phase 3: add block offsets; init cursors; write rowstart[N].
__global__ void k_scan3(void) {
    int idx = blockIdx.x * blockDim.x + threadIdx.x;
    if (idx < N_NODES) {
        int r = g_rowstart[idx] + g_boff[idx >> 10];
        g_rowstart[idx] = r;
        g_cursor[idx]   = r;
    }
    if (idx == 0) g_rowstart[N_NODES] = g_boff[NB1];
}

__global__ void k_scatter(const void* __restrict__ ei) {
    int e = blockIdx.x * blockDim.x + threadIdx.x;
    if (e < N_EDGES) {
        int sidx = edge_at(ei, 0, e);
        int d    = edge_at(ei, 1, e);
        if (d >= 0 && d < N_NODES && sidx >= 0 && sidx < N_NODES) {
            int pos = atomicAdd(&g_cursor[d], 1);
            if (pos >= 0 && pos < N_EDGES) g_csr[pos] = sidx;
        }
    }
}

// -------------------- bf16-split tensor-core GEMM --------------------------
// C[M,128] = A[M,K] @ B[K,128], fp32 in/out, K % 32 == 0.
// Block 128x128, BK=32 fp32; 8 warps (2x4), warp tile 64x32,
// mma.sync.m16n8k16 bf16, 3 split terms.
#define GBK 32
#define SAPITCH (GBK + 8)    // bf16 elems per A smem row
#define SBPITCH (GBK + 8)    // bf16 elems per B smem row (transposed [n][k])

__device__ __forceinline__ void mma_bf16(float* c, const unsigned* a,
                                         const unsigned* b) {
    asm volatile(
        "mma.sync.aligned.m16n8k16.row.col.f32.bf16.bf16.f32 "
        "{%0,%1,%2,%3}, {%4,%5,%6,%7}, {%8,%9}, {%0,%1,%2,%3};"
        : "+f"(c[0]), "+f"(c[1]), "+f"(c[2]), "+f"(c[3])
        : "r"(a[0]), "r"(a[1]), "r"(a[2]), "r"(a[3]), "r"(b[0]), "r"(b[1]));
}

__device__ __forceinline__ void split_bf16(float x, __nv_bfloat16& hi,
                                           __nv_bfloat16& lo) {
    hi = __float2bfloat16_rn(x);
    lo = __float2bfloat16_rn(x - __bfloat162float(hi));
}

__global__ void __launch_bounds__(256)
k_gemm_bf16(const float* __restrict__ A, const float* __restrict__ B,
            float* __restrict__ C, int M, int K) {
    __shared__ __nv_bfloat16 sA_hi[128 * SAPITCH];
    __shared__ __nv_bfloat16 sA_lo[128 * SAPITCH];
    __shared__ __nv_bfloat16 sB_hi[128 * SBPITCH];   // transposed: [n][k]
    __shared__ __nv_bfloat16 sB_lo[128 * SBPITCH];

    int tid   = threadIdx.x;
    int lane  = tid & 31;
    int wid   = tid >> 5;
    int warpM = wid >> 2;            // 0..1 -> m offset *64
    int warpN = wid & 3;             // 0..3 -> n offset *32
    int m0    = blockIdx.x * 128;

    float acc[4][4][4];              // [im][in][frag]
    #pragma unroll
    for (int i = 0; i < 4; i++)
        #pragma unroll
        for (int j = 0; j < 4; j++)
            #pragma unroll
            for (int r = 0; r < 4; r++) acc[i][j][r] = 0.f;

    // global-load mappings (4 float4 each for A and B per chunk)
    // A: 128 rows x 32 cols -> 1024 float4; row = lin/8, c4 = lin%8
    // B: 32 rows x 128 cols -> 1024 float4; row = lin/32, c4 = lin%32
    for (int k0 = 0; k0 < K; k0 += GBK) {
        float4 fa[4], fb[4];
        #pragma unroll
        for (int i = 0; i < 4; i++) {
            int lin = i * 256 + tid;
            int ar = lin >> 3, ac4 = lin & 7;
            int r = m0 + ar;
            fa[i] = (r < M) ? *(const float4*)&A[(size_t)r * K + k0 + ac4 * 4]
                            : make_float4(0.f, 0.f, 0.f, 0.f);
            int br = lin >> 5, bc4 = lin & 31;
            fb[i] = *(const float4*)&B[(size_t)(k0 + br) * 128 + bc4 * 4];
        }
        __syncthreads();   // previous iteration's reads complete
        #pragma unroll
        for (int i = 0; i < 4; i++) {
            int lin = i * 256 + tid;
            int ar = lin >> 3, ac = (lin & 7) * 4;
            __nv_bfloat16 h0, l0, h1, l1, h2, l2, h3, l3;
            split_bf16(fa[i].x, h0, l0); split_bf16(fa[i].y, h1, l1);
            split_bf16(fa[i].z, h2, l2); split_bf16(fa[i].w, h3, l3);
            __nv_bfloat162* ph = (__nv_bfloat162*)&sA_hi[ar * SAPITCH + ac];
            __nv_bfloat162* pl = (__nv_bfloat162*)&sA_lo[ar * SAPITCH + ac];
            ph[0] = __halves2bfloat162(h0, h1); ph[1] = __halves2bfloat162(h2, h3);
            pl[0] = __halves2bfloat162(l0, l1); pl[1] = __halves2bfloat162(l2, l3);

            int bk = lin >> 5, bn = (lin & 31) * 4;
            split_bf16(fb[i].x, h0, l0); split_bf16(fb[i].y, h1, l1);
            split_bf16(fb[i].z, h2, l2); split_bf16(fb[i].w, h3, l3);
            sB_hi[(bn + 0) * SBPITCH + bk] = h0; sB_lo[(bn + 0) * SBPITCH + bk] = l0;
            sB_hi[(bn + 1) * SBPITCH + bk] = h1; sB_lo[(bn + 1) * SBPITCH + bk] = l1;
            sB_hi[(bn + 2) * SBPITCH + bk] = h2; sB_lo[(bn + 2) * SBPITCH + bk] = l2;
            sB_hi[(bn + 3) * SBPITCH + bk] = h3; sB_lo[(bn + 3) * SBPITCH + bk] = l3;
        }
        __syncthreads();

        #pragma unroll
        for (int ks = 0; ks < 2; ks++) {
            int kc = ks * 16 + (lane & 3) * 2;
            unsigned ahi[4][4], alo[4][4], bhi[4][2], blo[4][2];
            #pragma unroll
            for (int im = 0; im < 4; im++) {
                int r0 = warpM * 64 + im * 16 + (lane >> 2);
                ahi[im][0] = *(unsigned*)&sA_hi[r0 * SAPITCH + kc];
                ahi[im][1] = *(unsigned*)&sA_hi[(r0 + 8) * SAPITCH + kc];
                ahi[im][2] = *(unsigned*)&sA_hi[r0 * SAPITCH + kc + 8];
                ahi[im][3] = *(unsigned*)&sA_hi[(r0 + 8) * SAPITCH + kc + 8];
                alo[im][0] = *(unsigned*)&sA_lo[r0 * SAPITCH + kc];
                alo[im][1] = *(unsigned*)&sA_lo[(r0 + 8) * SAPITCH + kc];
                alo[im][2] = *(unsigned*)&sA_lo[r0 * SAPITCH + kc + 8];
                alo[im][3] = *(unsigned*)&sA_lo[(r0 + 8) * SAPITCH + kc + 8];
            }
            #pragma unroll
            for (int in = 0; in < 4; in++) {
                int n = warpN * 32 + in * 8 + (lane >> 2);
                bhi[in][0] = *(unsigned*)&sB_hi[n * SBPITCH + kc];
                bhi[in][1] = *(unsigned*)&sB_hi[n * SBPITCH + kc + 8];
                blo[in][0] = *(unsigned*)&sB_lo[n * SBPITCH + kc];
                blo[in][1] = *(unsigned*)&sB_lo[n * SBPITCH + kc + 8];
            }
            #pragma unroll
            for (int im = 0; im < 4; im++)
                #pragma unroll
                for (int in = 0; in < 4; in++) {
                    mma_bf16(acc[im][in], ahi[im], bhi[in]);
                    mma_bf16(acc[im][in], ahi[im], blo[in]);
                    mma_bf16(acc[im][in], alo[im], bhi[in]);
                }
        }
    }

    // epilogue: c0,c1 at (row, col..col+1); c2,c3 at (row+8, col..col+1)
    #pragma unroll
    for (int im = 0; im < 4; im++) {
        int r = m0 + warpM * 64 + im * 16 + (lane >> 2);
        #pragma unroll
        for (int in = 0; in < 4; in++) {
            int c = warpN * 32 + in * 8 + (lane & 3) * 2;
            if (r < M)
                *(float2*)&C[(size_t)r * 128 + c] =
                    make_float2(acc[im][in][0], acc[im][in][1]);
            if (r + 8 < M)
                *(float2*)&C[(size_t)(r + 8) * 128 + c] =
                    make_float2(acc[im][in][2], acc[im][in][3]);
        }
    }
}

// -------------------- pack [W_mu | W_ls] -> g_wcat -------------------------
__global__ void k_packw(const float* __restrict__ Wmu,
                        const float* __restrict__ Wls) {
    int i = blockIdx.x * blockDim.x + threadIdx.x;
    if (i < C_HID * C_HID) {
        int k = i >> 7, j = i & 127;
        g_wcat[i] = (j < 64) ? Wmu[k * 64 + j] : Wls[k * 64 + (j - 64)];
    }
}

// -------------------- aggregation: warp per node, 128 channels -------------
__device__ __forceinline__ float4 agg_node(const float4* __restrict__ t,
                                           int d, int lane) {
    float dv = g_dinv[d];
    float4 v = t[d * 32 + lane];
    float w  = dv * dv;
    float4 acc = make_float4(w * v.x, w * v.y, w * v.z, w * v.w);
    int beg = g_rowstart[d], end = g_rowstart[d + 1];
    int i = beg;
    for (; i + 1 < end; i += 2) {
        int s0 = g_csr[i], s1 = g_csr[i + 1];
        float w0 = dv * g_dinv[s0];
        float w1 = dv * g_dinv[s1];
        float4 u0 = __ldg(&t[s0 * 32 + lane]);
        float4 u1 = __ldg(&t[s1 * 32 + lane]);
        acc.x += w0 * u0.x + w1 * u1.x;
        acc.y += w0 * u0.y + w1 * u1.y;
        acc.z += w0 * u0.z + w1 * u1.z;
        acc.w += w0 * u0.w + w1 * u1.w;
    }
    if (i < end) {
        int s0 = g_csr[i];
        float w0 = dv * g_dinv[s0];
        float4 u0 = __ldg(&t[s0 * 32 + lane]);
        acc.x += w0 * u0.x; acc.y += w0 * u0.y;
        acc.z += w0 * u0.z; acc.w += w0 * u0.w;
    }
    return acc;
}

__global__ void __launch_bounds__(256)
k_agg1(const float* __restrict__ b1) {
    int gw = (blockIdx.x * blockDim.x + threadIdx.x) >> 5;
    if (gw >= N_NODES) return;
    int lane = threadIdx.x & 31;
    float4 acc = agg_node(g_t1, gw, lane);
    float4 bb = *(const float4*)&b1[lane * 4];
    acc.x = fmaxf(acc.x + bb.x, 0.f);
    acc.y = fmaxf(acc.y + bb.y, 0.f);
    acc.z = fmaxf(acc.z + bb.z, 0.f);
    acc.w = fmaxf(acc.w + bb.w, 0.f);
    g_h[gw * 32 + lane] = acc;
}

__global__ void __launch_bounds__(256)
k_agg2(const float* __restrict__ b_mu, const float* __restrict__ b_ls,
       float* __restrict__ out) {
    int gw = (blockIdx.x * blockDim.x + threadIdx.x) >> 5;
    if (gw >= N_NODES) return;
    int lane = threadIdx.x & 31;
    float4 acc = agg_node(g_t2, gw, lane);
    int c = lane * 4;
    if (c < 64) {
        float4 bb = *(const float4*)&b_mu[c];
        acc.x += bb.x; acc.y += bb.y; acc.z += bb.z; acc.w += bb.w;
        *(float4*)&out[(size_t)gw * 64 + c] = acc;
    } else {
        float4 bb = *(const float4*)&b_ls[c - 64];
        acc.x += bb.x; acc.y += bb.y; acc.z += bb.z; acc.w += bb.w;
        *(float4*)&out[(size_t)N_NODES * 64 + (size_t)gw * 64 + (c - 64)] = acc;
    }
}

// -------------------- launch -----------------------------------------------
extern "C" void kernel_launch(void* const* d_in, const int* in_sizes, int n_in,
                              void* d_out, int out_size) {
    const float* x    = (const float*)d_in[0];
    const void*  ei   = d_in[1];                 // [2, E], int32 OR int64
    const float* W1   = (const float*)d_in[2];
    const float* b1   = (const float*)d_in[3];
    const float* Wmu  = (const float*)d_in[4];
    const float* bmu  = (const float*)d_in[5];
    const float* Wls  = (const float*)d_in[6];
    const float* bls  = (const float*)d_in[7];
    float*       out  = (float*)d_out;

    (void)in_sizes; (void)n_in; (void)out_size;

    void *p_t1 = nullptr, *p_h = nullptr, *p_t2 = nullptr, *p_wcat = nullptr;
    cudaGetSymbolAddress(&p_t1,   g_t1);
    cudaGetSymbolAddress(&p_h,    g_h);
    cudaGetSymbolAddress(&p_t2,   g_t2);
    cudaGetSymbolAddress(&p_wcat, g_wcat);

    // Graph preprocessing
    k_detect <<<1, 1>>>((const unsigned int*)ei);
    k_set_deg<<<(N_NODES + 255) / 256, 256>>>();
    k_count  <<<(N_EDGES + 255) / 256, 256>>>(ei);
    k_scan1  <<<NB1, 1024>>>();
    k_scan2  <<<1, 128>>>();
    k_scan3  <<<(N_NODES + 255) / 256, 256>>>();
    k_scatter<<<(N_EDGES + 255) / 256, 256>>>(ei);

    // Layer 1
    k_gemm_bf16<<<(N_NODES + 127) / 128, 256>>>(x, W1, (float*)p_t1,
                                                N_NODES, C_IN);
    k_agg1<<<(N_NODES * 32 + 255) / 256, 256>>>(b1);

    // Layers 2+3 fused (mu | logstd)
    k_packw<<<(C_HID * C_HID + 255) / 256, 256>>>(Wmu, Wls);
    k_gemm_bf16<<<(N_NODES + 127) / 128, 256>>>((const float*)p_h,
                                                (const float*)p_wcat,
                                                (float*)p_t2, N_NODES, C_HID);
    k_agg2<<<(N_NODES * 32 + 255) / 256, 256>>>(bmu, bls, out);
}

// round 9
// speedup vs baseline: 1.7489x; 1.3819x over previous
#include <cuda_runtime.h>
#include <cuda_bf16.h>
#include <cstdint>

// ---------------------------------------------------------------------------
// VariationalEncoder (3-layer GCN VGAE), N=100000, E=1600000, 512->128->{64,64}
// R9 = R8 minus the static attr guard (banned by harness rules; only code-side
// suspect for the container failure). Pipeline:
//  * pre-split x -> (x_hi, x_lo) bf16 in a streaming pass
//  * weights pre-split + pre-transposed [n][k]
//  * agg1 emits h as (hi,lo) bf16 pair directly
//  * GEMM: pure bf16 tiles, cp.async double-buffer (BK=64), 512 thr,
//    4x4 warps, 32x32 warp tile, 3-term split mma
// ---------------------------------------------------------------------------

#define N_NODES 100000
#define N_EDGES 1600000
#define C_IN    512
#define C_HID   128
#define NB1     ((N_NODES + 1023) / 1024)

// -------------------- device scratch ---------------------------------------
__device__ int    g_is64;
__device__ int    g_deg[N_NODES];
__device__ float  g_dinv[N_NODES];
__device__ int    g_rowstart[N_NODES + 1];
__device__ int    g_cursor[N_NODES];
__device__ int    g_bsum[NB1];
__device__ int    g_boff[NB1 + 1];
__device__ int    g_csr[N_EDGES];
__device__ __nv_bfloat16 g_xhi[(size_t)N_NODES * C_IN];
__device__ __nv_bfloat16 g_xlo[(size_t)N_NODES * C_IN];
__device__ __nv_bfloat16 g_w1thi[C_HID * C_IN];   // [n][k] transposed
__device__ __nv_bfloat16 g_w1tlo[C_HID * C_IN];
__device__ __nv_bfloat16 g_wcthi[C_HID * C_HID];  // [n][k], n = [mu|ls]
__device__ __nv_bfloat16 g_wctlo[C_HID * C_HID];
__device__ __nv_bfloat16 g_hhi[(size_t)N_NODES * C_HID];
__device__ __nv_bfloat16 g_hlo[(size_t)N_NODES * C_HID];
__device__ float4 g_t1[N_NODES * 32];   // [N,128] fp32
__device__ float4 g_t2[N_NODES * 32];   // [N,128] fp32

// -------------------- helpers ----------------------------------------------
__device__ __forceinline__ void splitf(float x, __nv_bfloat16& hi,
                                       __nv_bfloat16& lo) {
    hi = __float2bfloat16_rn(x);
    lo = __float2bfloat16_rn(x - __bfloat162float(hi));
}
__device__ __forceinline__ unsigned pack2(__nv_bfloat16 a, __nv_bfloat16 b) {
    return (unsigned)__bfloat16_as_ushort(a) |
           ((unsigned)__bfloat16_as_ushort(b) << 16);
}

// -------------------- dtype detection --------------------------------------
__global__ void k_detect(const unsigned int* __restrict__ w) {
    bool is64 = true;
    #pragma unroll
    for (int i = 0; i < 8; i++)
        if (w[2 * i + 1] != 0u) is64 = false;
    g_is64 = is64 ? 1 : 0;
}

__device__ __forceinline__ int edge_at(const void* __restrict__ ei,
                                       int row, int e) {
    if (g_is64)
        return (int)((const long long*)ei)[(size_t)row * N_EDGES + e];
    return ((const int*)ei)[(size_t)row * N_EDGES + e];
}

// -------------------- splits -----------------------------------------------
__global__ void k_splitx(const float4* __restrict__ x) {
    size_t i = (size_t)blockIdx.x * blockDim.x + threadIdx.x;   // float4 idx
    if (i >= (size_t)N_NODES * C_IN / 4) return;
    float4 v = x[i];
    __nv_bfloat16 h0, l0, h1, l1, h2, l2, h3, l3;
    splitf(v.x, h0, l0); splitf(v.y, h1, l1);
    splitf(v.z, h2, l2); splitf(v.w, h3, l3);
    uint2 uh = make_uint2(pack2(h0, h1), pack2(h2, h3));
    uint2 ul = make_uint2(pack2(l0, l1), pack2(l2, l3));
    *(uint2*)&g_xhi[i * 4] = uh;
    *(uint2*)&g_xlo[i * 4] = ul;
}

__global__ void k_splitw1(const float* __restrict__ W1) {
    int i = blockIdx.x * blockDim.x + threadIdx.x;   // over 512*128
    if (i >= C_IN * C_HID) return;
    int k = i >> 7, n = i & 127;
    __nv_bfloat16 h, l;
    splitf(W1[i], h, l);
    g_w1thi[n * C_IN + k] = h;
    g_w1tlo[n * C_IN + k] = l;
}

__global__ void k_packwt(const float* __restrict__ Wmu,
                         const float* __restrict__ Wls) {
    int i = blockIdx.x * blockDim.x + threadIdx.x;   // over 128*128
    if (i >= C_HID * C_HID) return;
    int k = i >> 7, n = i & 127;
    float w = (n < 64) ? Wmu[k * 64 + n] : Wls[k * 64 + (n - 64)];
    __nv_bfloat16 h, l;
    splitf(w, h, l);
    g_wcthi[n * C_HID + k] = h;
    g_wctlo[n * C_HID + k] = l;
}

// -------------------- graph preprocessing ----------------------------------
__global__ void k_set_deg(void) {
    int i = blockIdx.x * blockDim.x + threadIdx.x;
    if (i < N_NODES) g_deg[i] = 1;
}

__global__ void k_count(const void* __restrict__ ei) {
    int e = blockIdx.x * blockDim.x + threadIdx.x;
    if (e < N_EDGES) {
        int d = edge_at(ei, 1, e);
        if (d >= 0 && d < N_NODES) atomicAdd(&g_deg[d], 1);
    }
}

__global__ void __launch_bounds__(1024) k_scan1(void) {
    int tid  = threadIdx.x;
    int idx  = blockIdx.x * 1024 + tid;
    int lane = tid & 31, wid = tid >> 5;
    int deg = (idx < N_NODES) ? g_deg[idx] : 1;
    int v   = (idx < N_NODES) ? (deg - 1) : 0;
    if (idx < N_NODES) g_dinv[idx] = rsqrtf((float)deg);
    int incl = v;
    #pragma unroll
    for (int off = 1; off < 32; off <<= 1) {
        int t = __shfl_up_sync(0xffffffffu, incl, off);
        if (lane >= off) incl += t;
    }
    __shared__ int wsum[32];
    if (lane == 31) wsum[wid] = incl;
    __syncthreads();
    if (wid == 0) {
        int s = wsum[lane];
        #pragma unroll
        for (int off = 1; off < 32; off <<= 1) {
            int t = __shfl_up_sync(0xffffffffu, s, off);
            if (lane >= off) s += t;
        }
        wsum[lane] = s;
    }
    __syncthreads();
    int woff = (wid > 0) ? wsum[wid - 1] : 0;
    int excl = woff + incl - v;
    if (idx < N_NODES) g_rowstart[idx] = excl;
    if (tid == 1023) g_bsum[blockIdx.x] = woff + incl;
}

__global__ void k_scan2(void) {
    __shared__ int s[128];
    int tid = threadIdx.x;
    int v = (tid < NB1) ? g_bsum[tid] : 0;
    s[tid] = v;
    __syncthreads();
    #pragma unroll
    for (int off = 1; off < 128; off <<= 1) {
        int t = (tid >= off) ? s[tid - off] : 0;
        __syncthreads();
        s[tid] += t;
        __syncthreads();
    }
    int incl = s[tid];
    if (tid < NB1) g_boff[tid] = incl - v;
    if (tid == NB1 - 1) g_boff[NB1] = incl;
}

__global__ void k_scan3(void) {
    int idx = blockIdx.x * blockDim.x + threadIdx.x;
    if (idx < N_NODES) {
        int r = g_rowstart[idx] + g_boff[idx >> 10];
        g_rowstart[idx] = r;
        g_cursor[idx]   = r;
    }
    if (idx == 0) g_rowstart[N_NODES] = g_boff[NB1];
}

__global__ void k_scatter(const void* __restrict__ ei) {
    int e = blockIdx.x * blockDim.x + threadIdx.x;
    if (e < N_EDGES) {
        int sidx = edge_at(ei, 0, e);
        int d    = edge_at(ei, 1, e);
        if (d >= 0 && d < N_NODES && sidx >= 0 && sidx < N_NODES) {
            int pos = atomicAdd(&g_cursor[d], 1);
            if (pos >= 0 && pos < N_EDGES) g_csr[pos] = sidx;
        }
    }
}

// -------------------- bf16 tensor-core GEMM (pre-split operands) -----------
// C[M,128] = (Ahi+Alo)[M,K] @ (Bhi+Blo)^T[128,K]^T, 3-term split product.
// 512 threads, BM=128, BN=128, BK=64 bf16, cp.async double buffer.
#define GP      72                   // smem pitch in bf16 (144 B, 16B-aligned)
#define TILE_E  (128 * GP)           // elems per tile array
#define SMEM_BYTES (2 * 4 * TILE_E * 2)   // 2 buf x 4 arrays x bytes

__device__ __forceinline__ void mma_bf16(float* c, const unsigned* a,
                                         const unsigned* b) {
    asm volatile(
        "mma.sync.aligned.m16n8k16.row.col.f32.bf16.bf16.f32 "
        "{%0,%1,%2,%3}, {%4,%5,%6,%7}, {%8,%9}, {%0,%1,%2,%3};"
        : "+f"(c[0]), "+f"(c[1]), "+f"(c[2]), "+f"(c[3])
        : "r"(a[0]), "r"(a[1]), "r"(a[2]), "r"(a[3]), "r"(b[0]), "r"(b[1]));
}

__device__ __forceinline__ void cp16(unsigned s, const void* g) {
    asm volatile("cp.async.cg.shared.global [%0], [%1], 16;\n"
                 :: "r"(s), "l"(g));
}

__global__ void __launch_bounds__(512)
k_gemm(const __nv_bfloat16* __restrict__ Ahi,
       const __nv_bfloat16* __restrict__ Alo,
       const __nv_bfloat16* __restrict__ Bthi,   // [128][K]
       const __nv_bfloat16* __restrict__ Btlo,
       float* __restrict__ C, int M, int K) {
    extern __shared__ __nv_bfloat16 sm[];
    unsigned smbase = (unsigned)__cvta_generic_to_shared(sm);

    int tid   = threadIdx.x;
    int lane  = tid & 31;
    int wid   = tid >> 5;
    int warpM = wid >> 2;            // 0..3 -> m * 32
    int warpN = wid & 3;             // 0..3 -> n * 32
    int m0    = blockIdx.x * 128;
    int S     = K / 64;

    const __nv_bfloat16* gsrc[4] = {Ahi, Alo, Bthi, Btlo};

    float acc[2][4][4];
    #pragma unroll
    for (int i = 0; i < 2; i++)
        #pragma unroll
        for (int j = 0; j < 4; j++)
            #pragma unroll
            for (int r = 0; r < 4; r++) acc[i][j][r] = 0.f;

    auto issue = [&](int s) {
        int buf = s & 1;
        int k0  = s * 64;
        #pragma unroll
        for (int i = 0; i < 8; i++) {
            int c    = i * 512 + tid;         // 0..4095
            int arr  = c >> 10;               // 0..3
            int row  = (c >> 3) & 127;
            int c16  = c & 7;
            int gr;
            if (arr < 2) { gr = m0 + row; if (gr >= M) gr = 0; }  // A rows
            else         { gr = row; }                            // B rows
            const __nv_bfloat16* g = gsrc[arr] + (size_t)gr * K + k0 + c16 * 8;
            unsigned d = smbase +
                (unsigned)((buf * 4 + arr) * TILE_E + row * GP + c16 * 8) * 2;
            cp16(d, g);
        }
        asm volatile("cp.async.commit_group;\n");
    };

    issue(0);
    for (int s = 0; s < S; s++) {
        if (s + 1 < S) {
            issue(s + 1);
            asm volatile("cp.async.wait_group 1;\n");
        } else {
            asm volatile("cp.async.wait_group 0;\n");
        }
        __syncthreads();

        int buf = s & 1;
        const __nv_bfloat16* pAhi = sm + (buf * 4 + 0) * TILE_E;
        const __nv_bfloat16* pAlo = sm + (buf * 4 + 1) * TILE_E;
        const __nv_bfloat16* pBhi = sm + (buf * 4 + 2) * TILE_E;
        const __nv_bfloat16* pBlo = sm + (buf * 4 + 3) * TILE_E;

        #pragma unroll
        for (int k16 = 0; k16 < 4; k16++) {
            int kc = k16 * 16 + (lane & 3) * 2;
            unsigned ahi[2][4], alo[2][4], bhi[4][2], blo[4][2];
            #pragma unroll
            for (int im = 0; im < 2; im++) {
                int r0 = warpM * 32 + im * 16 + (lane >> 2);
                ahi[im][0] = *(const unsigned*)&pAhi[r0 * GP + kc];
                ahi[im][1] = *(const unsigned*)&pAhi[(r0 + 8) * GP + kc];
                ahi[im][2] = *(const unsigned*)&pAhi[r0 * GP + kc + 8];
                ahi[im][3] = *(const unsigned*)&pAhi[(r0 + 8) * GP + kc + 8];
                alo[im][0] = *(const unsigned*)&pAlo[r0 * GP + kc];
                alo[im][1] = *(const unsigned*)&pAlo[(r0 + 8) * GP + kc];
                alo[im][2] = *(const unsigned*)&pAlo[r0 * GP + kc + 8];
                alo[im][3] = *(const unsigned*)&pAlo[(r0 + 8) * GP + kc + 8];
            }
            #pragma unroll
            for (int in = 0; in < 4; in++) {
                int n0 = warpN * 32 + in * 8 + (lane >> 2);
                bhi[in][0] = *(const unsigned*)&pBhi[n0 * GP + kc];
                bhi[in][1] = *(const unsigned*)&pBhi[n0 * GP + kc + 8];
                blo[in][0] = *(const unsigned*)&pBlo[n0 * GP + kc];
                blo[in][1] = *(const unsigned*)&pBlo[n0 * GP + kc + 8];
            }
            #pragma unroll
            for (int im = 0; im < 2; im++)
                #pragma unroll
                for (int in = 0; in < 4; in++) {
                    mma_bf16(acc[im][in], ahi[im], bhi[in]);
                    mma_bf16(acc[im][in], ahi[im], blo[in]);
                    mma_bf16(acc[im][in], alo[im], bhi[in]);
                }
        }
        __syncthreads();
    }

    #pragma unroll
    for (int im = 0; im < 2; im++) {
        int r = m0 + warpM * 32 + im * 16 + (lane >> 2);
        #pragma unroll
        for (int in = 0; in < 4; in++) {
            int c = warpN * 32 + in * 8 + (lane & 3) * 2;
            if (r < M)
                *(float2*)&C[(size_t)r * 128 + c] =
                    make_float2(acc[im][in][0], acc[im][in][1]);
            if (r + 8 < M)
                *(float2*)&C[(size_t)(r + 8) * 128 + c] =
                    make_float2(acc[im][in][2], acc[im][in][3]);
        }
    }
}

// -------------------- aggregation ------------------------------------------
__device__ __forceinline__ float4 agg_node(const float4* __restrict__ t,
                                           int d, int lane) {
    float dv = g_dinv[d];
    float4 v = t[d * 32 + lane];
    float w  = dv * dv;
    float4 acc = make_float4(w * v.x, w * v.y, w * v.z, w * v.w);
    int beg = g_rowstart[d], end = g_rowstart[d + 1];
    int i = beg;
    for (; i + 1 < end; i += 2) {
        int s0 = g_csr[i], s1 = g_csr[i + 1];
        float w0 = dv * g_dinv[s0];
        float w1 = dv * g_dinv[s1];
        float4 u0 = __ldg(&t[s0 * 32 + lane]);
        float4 u1 = __ldg(&t[s1 * 32 + lane]);
        acc.x += w0 * u0.x + w1 * u1.x;
        acc.y += w0 * u0.y + w1 * u1.y;
        acc.z += w0 * u0.z + w1 * u1.z;
        acc.w += w0 * u0.w + w1 * u1.w;
    }
    if (i < end) {
        int s0 = g_csr[i];
        float w0 = dv * g_dinv[s0];
        float4 u0 = __ldg(&t[s0 * 32 + lane]);
        acc.x += w0 * u0.x; acc.y += w0 * u0.y;
        acc.z += w0 * u0.z; acc.w += w0 * u0.w;
    }
    return acc;
}

// h = relu(A_hat t1 + b1) emitted as (hi, lo) bf16 pair for GEMM2.
__global__ void __launch_bounds__(256)
k_agg1(const float* __restrict__ b1) {
    int gw = (blockIdx.x * blockDim.x + threadIdx.x) >> 5;
    if (gw >= N_NODES) return;
    int lane = threadIdx.x & 31;
    float4 acc = agg_node(g_t1, gw, lane);
    float4 bb = *(const float4*)&b1[lane * 4];
    acc.x = fmaxf(acc.x + bb.x, 0.f);
    acc.y = fmaxf(acc.y + bb.y, 0.f);
    acc.z = fmaxf(acc.z + bb.z, 0.f);
    acc.w = fmaxf(acc.w + bb.w, 0.f);
    __nv_bfloat16 h0, l0, h1, l1, h2, l2, h3, l3;
    splitf(acc.x, h0, l0); splitf(acc.y, h1, l1);
    splitf(acc.z, h2, l2); splitf(acc.w, h3, l3);
    size_t o = (size_t)gw * C_HID + lane * 4;
    *(uint2*)&g_hhi[o] = make_uint2(pack2(h0, h1), pack2(h2, h3));
    *(uint2*)&g_hlo[o] = make_uint2(pack2(l0, l1), pack2(l2, l3));
}

__global__ void __launch_bounds__(256)
k_agg2(const float* __restrict__ b_mu, const float* __restrict__ b_ls,
       float* __restrict__ out) {
    int gw = (blockIdx.x * blockDim.x + threadIdx.x) >> 5;
    if (gw >= N_NODES) return;
    int lane = threadIdx.x & 31;
    float4 acc = agg_node(g_t2, gw, lane);
    int c = lane * 4;
    if (c < 64) {
        float4 bb = *(const float4*)&b_mu[c];
        acc.x += bb.x; acc.y += bb.y; acc.z += bb.z; acc.w += bb.w;
        *(float4*)&out[(size_t)gw * 64 + c] = acc;
    } else {
        float4 bb = *(const float4*)&b_ls[c - 64];
        acc.x += bb.x; acc.y += bb.y; acc.z += bb.z; acc.w += bb.w;
        *(float4*)&out[(size_t)N_NODES * 64 + (size_t)gw * 64 + (c - 64)] = acc;
    }
}

// -------------------- launch -----------------------------------------------
extern "C" void kernel_launch(void* const* d_in, const int* in_sizes, int n_in,
                              void* d_out, int out_size) {
    const float* x    = (const float*)d_in[0];
    const void*  ei   = d_in[1];
    const float* W1   = (const float*)d_in[2];
    const float* b1   = (const float*)d_in[3];
    const float* Wmu  = (const float*)d_in[4];
    const float* bmu  = (const float*)d_in[5];
    const float* Wls  = (const float*)d_in[6];
    const float* bls  = (const float*)d_in[7];
    float*       out  = (float*)d_out;

    (void)in_sizes; (void)n_in; (void)out_size;

    void *p_xhi, *p_xlo, *p_w1thi, *p_w1tlo, *p_wcthi, *p_wctlo;
    void *p_hhi, *p_hlo, *p_t1, *p_t2;
    cudaGetSymbolAddress(&p_xhi,   g_xhi);
    cudaGetSymbolAddress(&p_xlo,   g_xlo);
    cudaGetSymbolAddress(&p_w1thi, g_w1thi);
    cudaGetSymbolAddress(&p_w1tlo, g_w1tlo);
    cudaGetSymbolAddress(&p_wcthi, g_wcthi);
    cudaGetSymbolAddress(&p_wctlo, g_wctlo);
    cudaGetSymbolAddress(&p_hhi,   g_hhi);
    cudaGetSymbolAddress(&p_hlo,   g_hlo);
    cudaGetSymbolAddress(&p_t1,    g_t1);
    cudaGetSymbolAddress(&p_t2,    g_t2);

    // Unconditional (idempotent, deterministic) — no static guard.
    cudaFuncSetAttribute(k_gemm,
        cudaFuncAttributeMaxDynamicSharedMemorySize, SMEM_BYTES);

    int nblk = (N_NODES + 127) / 128;

    // inputs -> split operands (no graph dependency)
    k_detect <<<1, 1>>>((const unsigned int*)ei);
    k_splitx <<<(N_NODES * (C_IN / 4) + 255) / 256, 256>>>((const float4*)x);
    k_splitw1<<<(C_IN * C_HID + 255) / 256, 256>>>(W1);

    // GEMM1 (ncu capture slot 4)
    k_gemm<<<nblk, 512, SMEM_BYTES>>>(
        (const __nv_bfloat16*)p_xhi, (const __nv_bfloat16*)p_xlo,
        (const __nv_bfloat16*)p_w1thi, (const __nv_bfloat16*)p_w1tlo,
        (float*)p_t1, N_NODES, C_IN);

    // graph preprocessing
    k_set_deg<<<(N_NODES + 255) / 256, 256>>>();
    k_count  <<<(N_EDGES + 255) / 256, 256>>>(ei);
    k_scan1  <<<NB1, 1024>>>();
    k_scan2  <<<1, 128>>>();
    k_scan3  <<<(N_NODES + 255) / 256, 256>>>();
    k_scatter<<<(N_EDGES + 255) / 256, 256>>>(ei);

    // layer 1 aggregate (emits split h)
    k_agg1<<<(N_NODES * 32 + 255) / 256, 256>>>(b1);

    // layers 2+3 fused
    k_packwt<<<(C_HID * C_HID + 255) / 256, 256>>>(Wmu, Wls);
    k_gemm<<<nblk, 512, SMEM_BYTES>>>(
        (const __nv_bfloat16*)p_hhi, (const __nv_bfloat16*)p_hlo,
        (const __nv_bfloat16*)p_wcthi, (const __nv_bfloat16*)p_wctlo,
        (float*)p_t2, N_NODES, C_HID);
    k_agg2<<<(N_NODES * 32 + 255) / 256, 256>>>(bmu, bls, out);
}